// round 17
// baseline (speedup 1.0000x reference)
#include <cuda_runtime.h>
#include <cstdint>

#define NN   4096
#define CAP  256          // max neighbors/row (mean ~83, sd ~9)
#define NG   64
#define OUTC 10

#define KCH  4            // K-split chunks for layer-0 GEMM (512/4 = 128)
#define GEMM0_BLOCKS (256 * KCH)
#define ADJ_BLOCKS   1024

// ---------------- scratch (device globals; no allocation allowed) ------------
__device__ int    g_deg[NN];
__device__ int    g_nbr[NN * CAP];             // byte-offset (j*256), asc per row
__device__ float  g_part[KCH * NN * 64];       // layer-0 GEMM partials (4 MB)
__device__ __align__(8) float g_fi[NN * 64];   // interleaved: [i][h*2+k]
__device__ float2 g_s1v[NN];                   // (head0, head1)
__device__ float2 g_s2v[NN];
__device__ float  g_h[NN * 192];               // concat of relu'd outputs

// ================= K1: K-split gemm0 chunks + adjacency build ================
__global__ __launch_bounds__(256) void gemm0_adj_kernel(
        const float* __restrict__ x, const float* __restrict__ adj,
        const float* __restrict__ W) {
    __shared__ union {
        struct { float xs[64][20]; float ws[64][64]; } g;
        struct { int wsum[8]; } a;
    } s;
    int tid  = threadIdx.x;
    int lane = tid & 31;

    if (blockIdx.x < GEMM0_BLOCKS) {
        // ---- 16-row x 64-col x 128-K partial tile ---------------------------
        int kc   = blockIdx.x & (KCH - 1);
        int tile = blockIdx.x >> 2;          // 0..255
        int row0 = tile * 16;
        int t  = tid & 63;                   // out col (k*32+h)
        int rg = tid >> 6;                   // 0..3

        float acc0 = 0.f, acc1 = 0.f, acc2 = 0.f, acc3 = 0.f;
        int k0 = kc * (512 / KCH);
        for (int t0 = k0; t0 < k0 + 512 / KCH; t0 += 64) {
            for (int idx = tid; idx < 16 * 64; idx += 256) {
                int r = idx >> 6, d = idx & 63;
                s.g.xs[d][r] = x[(size_t)(row0 + r) * 512 + t0 + d];
            }
            for (int idx = tid; idx < 64 * 64; idx += 256) {
                int d = idx >> 6, tt = idx & 63;
                int kk = tt >> 5, hh = tt & 31;
                s.g.ws[d][tt] = W[(size_t)kk * 512 * 32 + (size_t)(t0 + d) * 32 + hh];
            }
            __syncthreads();
#pragma unroll
            for (int dd = 0; dd < 64; ++dd) {
                float4 xv = *(const float4*)&s.g.xs[dd][rg * 4];
                float  wv = s.g.ws[dd][t];
                acc0 += xv.x * wv;
                acc1 += xv.y * wv;
                acc2 += xv.z * wv;
                acc3 += xv.w * wv;
            }
            __syncthreads();
        }
        float* pp = g_part + ((size_t)kc * NN + row0 + rg * 4) * 64 + t;
        pp[0]      = acc0;
        pp[64]     = acc1;
        pp[128]    = acc2;
        pp[192]    = acc3;
    } else {
        // ---- adjacency build: block per row, strided ------------------------
        int warp = tid >> 5;
        for (int row = blockIdx.x - GEMM0_BLOCKS; row < NN; row += ADJ_BLOCKS) {
            const float4* arow = (const float4*)(adj + (size_t)row * NN);
            int loc[16];
            int cnt = 0;
            int c0 = tid * 16;
#pragma unroll
            for (int v = 0; v < 4; ++v) {
                float4 q = arow[tid * 4 + v];
                if (q.x > 0.f) loc[cnt++] = c0 + v * 4 + 0;
                if (q.y > 0.f) loc[cnt++] = c0 + v * 4 + 1;
                if (q.z > 0.f) loc[cnt++] = c0 + v * 4 + 2;
                if (q.w > 0.f) loc[cnt++] = c0 + v * 4 + 3;
            }
            int xs = cnt;
#pragma unroll
            for (int o = 1; o < 32; o <<= 1) {
                int y = __shfl_up_sync(0xffffffffu, xs, o);
                if (lane >= o) xs += y;
            }
            if (lane == 31) s.a.wsum[warp] = xs;
            __syncthreads();
            if (tid == 0) {
                int acc = 0;
#pragma unroll
                for (int w = 0; w < 8; ++w) { int y = s.a.wsum[w]; s.a.wsum[w] = acc; acc += y; }
                g_deg[row] = acc;
            }
            __syncthreads();
            int base = s.a.wsum[warp] + (xs - cnt);
            for (int u = 0; u < cnt; ++u) {
                int pos = base + u;
                if (pos < CAP) g_nbr[row * CAP + pos] = loc[u] * 256; // byte off
            }
            __syncthreads();
        }
    }
}

// ================= combine partials + bias -> g_fi, fused s1/s2 ==============
__global__ __launch_bounds__(256) void combine_kernel(
        const float* __restrict__ b,
        const float* __restrict__ a1w, const float* __restrict__ a1b,
        const float* __restrict__ a2w, const float* __restrict__ a2b) {
    int warp = threadIdx.x >> 5;
    int lane = threadIdx.x & 31;
    int i    = blockIdx.x * 8 + warp;    // row, grid 512

    float f0 = b[lane];                  // head0 col = lane
    float f1 = b[32 + lane];             // head1 col = 32+lane
#pragma unroll
    for (int p = 0; p < KCH; ++p) {
        const float* pp = g_part + ((size_t)p * NN + i) * 64;
        f0 += pp[lane];
        f1 += pp[32 + lane];
    }
    ((float2*)g_fi)[(size_t)i * 32 + lane] = make_float2(f0, f1);

    float v10 = f0 * a1w[lane], v11 = f1 * a1w[32 + lane];
    float v20 = f0 * a2w[lane], v21 = f1 * a2w[32 + lane];
#pragma unroll
    for (int o = 16; o > 0; o >>= 1) {
        v10 += __shfl_down_sync(0xffffffffu, v10, o);
        v11 += __shfl_down_sync(0xffffffffu, v11, o);
        v20 += __shfl_down_sync(0xffffffffu, v20, o);
        v21 += __shfl_down_sync(0xffffffffu, v21, o);
    }
    if (lane == 0) {
        g_s1v[i] = make_float2(v10 + a1b[0], v11 + a1b[1]);
        g_s2v[i] = make_float2(v20 + a2b[0], v21 + a2b[1]);
    }
}

// ================= attn: 4 row-groups x 64 threads, unroll-8 gather ==========
__global__ __launch_bounds__(256) void attn_kernel(int layer) {
    int tid  = threadIdx.x;
    int grp  = tid >> 6;                 // 0..3
    int gtid = tid & 63;
    int gw   = gtid >> 5;                // warp within group
    int lane = tid & 31;
    int i    = blockIdx.x * 4 + grp;

    __shared__ float4 ed[4][CAP];        // (byteoff_bits, w0, w1, -)
    __shared__ float2 sred[4][32];
    __shared__ float2 sds[4][2];

    int deg = min(g_deg[i], CAP);
    const int* __restrict__ nb = g_nbr + i * CAP;

    float2 s1 = g_s1v[i];
    float d0 = 0.f, d1 = 0.f;
    for (int idx = gtid; idx < deg; idx += 64) {
        int joff = nb[idx];              // j*256 bytes
        float2 s2 = *(const float2*)((const char*)g_s2v + (joff >> 5));
        float e0 = s1.x + s2.x; e0 = (e0 >= 0.f) ? e0 : 0.01f * e0;
        float e1 = s1.y + s2.y; e1 = (e1 >= 0.f) ? e1 : 0.01f * e1;
        float w0 = __expf(e0);           // |e| small: no max needed
        float w1 = __expf(e1);
        ed[grp][idx] = make_float4(__int_as_float(joff), w0, w1, 0.f);
        d0 += w0; d1 += w1;
    }
#pragma unroll
    for (int o = 16; o > 0; o >>= 1) {
        d0 += __shfl_xor_sync(0xffffffffu, d0, o);
        d1 += __shfl_xor_sync(0xffffffffu, d1, o);
    }
    if (lane == 0) sds[grp][gw] = make_float2(d0, d1);
    asm volatile("bar.sync %0, 64;" :: "r"(grp + 1) : "memory");

    const char* __restrict__ fbase = (const char*)g_fi + lane * 8;
    float2 a0 = {0.f, 0.f}, a1 = {0.f, 0.f}, a2 = {0.f, 0.f}, a3 = {0.f, 0.f};
    const float4* edg = ed[grp];
    int e = gw;
    for (; e + 14 < deg; e += 16) {      // warp-interleaved stride-2, unroll 8
        float4 q0 = edg[e];
        float4 q1 = edg[e + 2];
        float4 q2 = edg[e + 4];
        float4 q3 = edg[e + 6];
        float4 q4 = edg[e + 8];
        float4 q5 = edg[e + 10];
        float4 q6 = edg[e + 12];
        float4 q7 = edg[e + 14];
        float2 f0 = *(const float2*)(fbase + __float_as_int(q0.x));
        float2 f1 = *(const float2*)(fbase + __float_as_int(q1.x));
        float2 f2 = *(const float2*)(fbase + __float_as_int(q2.x));
        float2 f3 = *(const float2*)(fbase + __float_as_int(q3.x));
        float2 f4 = *(const float2*)(fbase + __float_as_int(q4.x));
        float2 f5 = *(const float2*)(fbase + __float_as_int(q5.x));
        float2 f6 = *(const float2*)(fbase + __float_as_int(q6.x));
        float2 f7 = *(const float2*)(fbase + __float_as_int(q7.x));
        a0.x += q0.y * f0.x; a0.y += q0.z * f0.y;
        a1.x += q1.y * f1.x; a1.y += q1.z * f1.y;
        a2.x += q2.y * f2.x; a2.y += q2.z * f2.y;
        a3.x += q3.y * f3.x; a3.y += q3.z * f3.y;
        a0.x += q4.y * f4.x; a0.y += q4.z * f4.y;
        a1.x += q5.y * f5.x; a1.y += q5.z * f5.y;
        a2.x += q6.y * f6.x; a2.y += q6.z * f6.y;
        a3.x += q7.y * f7.x; a3.y += q7.z * f7.y;
    }
    for (; e < deg; e += 2) {
        float4 q0 = edg[e];
        float2 f0 = *(const float2*)(fbase + __float_as_int(q0.x));
        a0.x += q0.y * f0.x; a0.y += q0.z * f0.y;
    }
    float2 acc;
    acc.x = (a0.x + a1.x) + (a2.x + a3.x);
    acc.y = (a0.y + a1.y) + (a2.y + a3.y);
    if (gw == 1) sred[grp][lane] = acc;
    asm volatile("bar.sync %0, 64;" :: "r"(grp + 1) : "memory");

    if (gw == 0) {
        float2 p1 = sred[grp][lane];
        float2 u0 = sds[grp][0], u1 = sds[grp][1];
        float den0 = u0.x + u1.x;
        float den1 = u0.y + u1.y;
        float o0 = (acc.x + p1.x) / den0; o0 = (o0 > 0.f) ? o0 : 0.f;
        float o1 = (acc.y + p1.y) / den1; o1 = (o1 > 0.f) ? o1 : 0.f;
        float* hp = g_h + (size_t)i * 192 + layer * 64;
        hp[lane]      = o0;
        hp[32 + lane] = o1;
    }
}

// ================= layers 1/2 GEMM: one warp per row (in_dim=64) =============
__global__ __launch_bounds__(256) void gemm_small_kernel(
        const float* __restrict__ W,   const float* __restrict__ b,
        const float* __restrict__ a1w, const float* __restrict__ a1b,
        const float* __restrict__ a2w, const float* __restrict__ a2b,
        int layer) {
    int warp = threadIdx.x >> 5;
    int lane = threadIdx.x & 31;
    int i    = blockIdx.x * 8 + warp;    // row, grid 512

    const float* in = g_h + (layer - 1) * 64 + (size_t)i * 192;
    float x0 = in[lane];
    float x1 = in[lane + 32];

    float acc0 = 0.f, acc1 = 0.f;
    const float* W0 = W;                 // head0: W[0][d][h]
    const float* W1 = W + 64 * 32;       // head1
#pragma unroll
    for (int d = 0; d < 32; ++d) {
        float xd = __shfl_sync(0xffffffffu, x0, d);
        acc0 += xd * W0[d * 32 + lane];
        acc1 += xd * W1[d * 32 + lane];
    }
#pragma unroll
    for (int d = 0; d < 32; ++d) {
        float xd = __shfl_sync(0xffffffffu, x1, d);
        acc0 += xd * W0[(d + 32) * 32 + lane];
        acc1 += xd * W1[(d + 32) * 32 + lane];
    }
    acc0 += b[lane];
    acc1 += b[32 + lane];
    ((float2*)g_fi)[(size_t)i * 32 + lane] = make_float2(acc0, acc1);

    float v10 = acc0 * a1w[lane],      v11 = acc1 * a1w[32 + lane];
    float v20 = acc0 * a2w[lane],      v21 = acc1 * a2w[32 + lane];
#pragma unroll
    for (int o = 16; o > 0; o >>= 1) {
        v10 += __shfl_down_sync(0xffffffffu, v10, o);
        v11 += __shfl_down_sync(0xffffffffu, v11, o);
        v20 += __shfl_down_sync(0xffffffffu, v20, o);
        v21 += __shfl_down_sync(0xffffffffu, v21, o);
    }
    if (lane == 0) {
        g_s1v[i] = make_float2(v10 + a1b[0], v11 + a1b[1]);
        g_s2v[i] = make_float2(v20 + a2b[0], v21 + a2b[1]);
    }
}

// ================= pool + final linear + softmax =============================
__global__ void pool_kernel(const int* __restrict__ batch,
                            const float* __restrict__ Wf,
                            const float* __restrict__ bf,
                            float* __restrict__ out) {
    int g = blockIdx.x;
    int c = threadIdx.x;                 // 192

    int lo = 0, hi = NN;
    while (lo < hi) { int mid = (lo + hi) >> 1; if (batch[mid] < g) lo = mid + 1; else hi = mid; }
    int start = lo;
    lo = start; hi = NN;
    while (lo < hi) { int mid = (lo + hi) >> 1; if (batch[mid] < g + 1) lo = mid + 1; else hi = mid; }
    int end = lo;
    int cnt = end - start;

    float accv = 0.f;
    for (int i = start; i < end; ++i) accv += g_h[(size_t)i * 192 + c];

    __shared__ float sp[192];
    __shared__ float lg[OUTC];
    sp[c] = accv / fmaxf((float)cnt, 1.f);
    __syncthreads();

    if (c < OUTC) {
        float a = bf[c];
        for (int d = 0; d < 192; ++d) a += sp[d] * Wf[d * OUTC + c];
        lg[c] = a;
    }
    __syncthreads();
    if (c < OUTC) {
        float mx = -1e30f;
#pragma unroll
        for (int o = 0; o < OUTC; ++o) mx = fmaxf(mx, lg[o]);
        float s = 0.f;
#pragma unroll
        for (int o = 0; o < OUTC; ++o) s += __expf(lg[o] - mx);
        out[g * OUTC + c] = __expf(lg[c] - mx) / s;
    }
}

// ================= launch ====================================================
extern "C" void kernel_launch(void* const* d_in, const int* in_sizes, int n_in,
                              void* d_out, int out_size) {
    const float* x     = (const float*)d_in[0];
    const float* adj   = (const float*)d_in[1];
    const int*   batch = (const int*)  d_in[2];
    const float* p[20];
    for (int i = 0; i < 20; ++i) p[i] = (const float*)d_in[3 + i];

    gemm0_adj_kernel<<<GEMM0_BLOCKS + ADJ_BLOCKS, 256>>>(x, adj, p[0]);
    combine_kernel<<<NN / 8, 256>>>(p[1], p[2], p[3], p[4], p[5]);

    attn_kernel<<<NN / 4, 256>>>(0);

    for (int l = 1; l < 3; ++l) {
        gemm_small_kernel<<<NN / 8, 256>>>(p[l * 6 + 0], p[l * 6 + 1],
                                           p[l * 6 + 2], p[l * 6 + 3],
                                           p[l * 6 + 4], p[l * 6 + 5], l);
        attn_kernel<<<NN / 4, 256>>>(l);
    }

    pool_kernel<<<NG, 192>>>(batch, p[18], p[19], (float*)d_out);
}